// round 14
// baseline (speedup 1.0000x reference)
#include <cuda_runtime.h>
#include <cstdint>

// Problem constants (fixed shapes per setup_inputs)
#define N_PTS   65536
#define DLAT    64
#define KC      64
#define DDATA   512
#define ALPHA_F 0.001f
#define EPS_F   1e-8f
#define TILE_P  64
#define NT      (N_PTS / TILE_P)     // 1024 tiles of 64 points

// SMEM layout (floats), 128-thread CTA, 4 CTAs/SM:
//   eS/ct stride 72: B-frag bank = 8q+g (bijective); A-frag 8g+q (2-way, ok)
//   rT stride 68:    A-frag bank = 4g+q (bijective); rows 16B-aligned (68*4=272)
#define STRB 72
#define STRR 68
#define OFF_ES 0
#define OFF_CT (OFF_ES + 64 * STRB)        // 4608
#define OFF_RT (OFF_CT + 64 * STRB)        // 9216
#define OFF_C2 (OFF_RT + 64 * STRR)        // 13568
#define OFF_X2 (OFF_C2 + 64)               // 13632
#define OFF_RED (OFF_X2 + 64)              // 13696
#define SMEM_FLOATS (OFF_RED + 4)          // 13700
#define DSMEM_BYTES (SMEM_FLOATS * 4)      // 54800 -> 4 CTAs/SM (214KB/SM)

// Scratch (device globals; no allocation allowed). Triple-buffered accumulators:
// iter j reads (j-1)%3, writes j%3, zeroes (j+1)%3 (idle buffer) — all disjoint.
__device__ float g_C[KC * DLAT];
__device__ float g_num[3][KC * DLAT];
__device__ float g_den[3][KC];
__device__ float g_loss;
__device__ float g_dec;

// ---------------------------------------------------------------------------
// tf32 m16n8k8 MMA (operands are raw fp32 bits; HW truncates to tf32)
// ---------------------------------------------------------------------------
__device__ __forceinline__ void mma8(float* c, uint32_t a0, uint32_t a1,
                                     uint32_t a2, uint32_t a3,
                                     uint32_t b0, uint32_t b1) {
    asm volatile(
        "mma.sync.aligned.m16n8k8.row.col.f32.tf32.tf32.f32 "
        "{%0,%1,%2,%3}, {%4,%5,%6,%7}, {%8,%9}, {%0,%1,%2,%3};"
        : "+f"(c[0]), "+f"(c[1]), "+f"(c[2]), "+f"(c[3])
        : "r"(a0), "r"(a1), "r"(a2), "r"(a3), "r"(b0), "r"(b1));
}
__device__ __forceinline__ uint32_t s2u(const void* p) {
    uint32_t a;
    asm("{ .reg .u64 t; cvta.to.shared.u64 t, %1; cvt.u32.u64 %0, t; }" : "=r"(a) : "l"(p));
    return a;
}
__device__ __forceinline__ void cp16(uint32_t dst, const void* src) {
    asm volatile("cp.async.ca.shared.global [%0], [%1], 16;" :: "r"(dst), "l"(src) : "memory");
}
__device__ __forceinline__ void cp_wait_all() {
    asm volatile("cp.async.commit_group;" ::: "memory");
    asm volatile("cp.async.wait_group 0;" ::: "memory");
}

// ---------------------------------------------------------------------------
// Zero accumulators (3 buffers) + scalars
// ---------------------------------------------------------------------------
__global__ void init_kernel() {
    int i = blockIdx.x * blockDim.x + threadIdx.x;
    if (i < 3 * KC * DLAT) ((float*)g_num)[i] = 0.f;
    if (i < 3 * KC)        ((float*)g_den)[i] = 0.f;
    if (i == 0) { g_loss = 0.f; g_dec = 0.f; }
}

// ---------------------------------------------------------------------------
// Decoder loss: sum((X - Dc)^2), float4 grid-stride, block-reduced atomicAdd
// ---------------------------------------------------------------------------
__global__ __launch_bounds__(256) void dec_kernel(const float4* __restrict__ X,
                                                  const float4* __restrict__ Dc,
                                                  int n4) {
    float acc = 0.f;
    int stride = gridDim.x * blockDim.x;
    for (int i = blockIdx.x * blockDim.x + threadIdx.x; i < n4; i += stride) {
        float4 a = X[i], b = Dc[i];
        float d0 = a.x - b.x, d1 = a.y - b.y, d2 = a.z - b.z, d3 = a.w - b.w;
        acc += d0 * d0 + d1 * d1 + d2 * d2 + d3 * d3;
    }
    __shared__ float red[8];
    #pragma unroll
    for (int o = 16; o; o >>= 1) acc += __shfl_xor_sync(0xffffffffu, acc, o);
    int w = threadIdx.x >> 5;
    if ((threadIdx.x & 31) == 0) red[w] = acc;
    __syncthreads();
    if (threadIdx.x < 32) {
        float v = (threadIdx.x < 8) ? red[threadIdx.x] : 0.f;
        #pragma unroll
        for (int o = 4; o; o >>= 1) v += __shfl_xor_sync(0xffffffffu, v, o);
        if (threadIdx.x == 0) atomicAdd(&g_dec, v);
    }
}

// ---------------------------------------------------------------------------
// Fused k-means iteration on tf32 mma.sync (m16n8k8), 128-thread CTAs,
// 64-point tiles, 4 CTAs/SM:
//   phase A: dot[p][k] = enc_tile @ C^T   (4 warps x 64 MMAs)
//   softmax over k (quad-lane reduction; x2 cancels in logits)
//   phase B: Cnum += r^T enc (persistent register accumulators across tiles)
//   last iter: loss += sum r * max(x2 + c2 - 2 dot, 0)
// ---------------------------------------------------------------------------
__global__ __launch_bounds__(128, 4) void assign_kernel(const float* __restrict__ enc,
                                                        int it) {
    extern __shared__ float sm[];
    float* eS  = sm + OFF_ES;
    float* ct  = sm + OFF_CT;
    float* rT  = sm + OFF_RT;
    float* c2s = sm + OFF_C2;
    float* x2s = sm + OFF_X2;
    float* red = sm + OFF_RED;

    int tid = threadIdx.x, lane = tid & 31, w = tid >> 5;   // w: 0..3
    int g = lane >> 2, q = lane & 3;
    int last = (it == 9);

    // ---- stage C (fp32) into scratch (rT+eS area), then ct + c2 ----
    float* csrc = rT;   // 4096 floats fit in rT(4352)
    if (it == 0) {
        for (int i = tid; i < KC * DLAT; i += 128) csrc[i] = g_C[i];
    } else {
        const float* nr = g_num[(it - 1) % 3];
        const float* dr = g_den[(it - 1) % 3];
        for (int i = tid; i < KC * DLAT; i += 128)
            csrc[i] = __fdividef(nr[i], dr[i >> 6] + EPS_F);
    }
    __syncthreads();
    for (int i = tid; i < KC * DLAT; i += 128) {
        int k = i & 63, d = i >> 6;
        ct[d * STRB + k] = csrc[i];            // ct[d][k] = C[k][d]
    }
    if (tid < KC) {
        float s = 0.f;
        #pragma unroll 8
        for (int d = 0; d < DLAT; d++) { float v = csrc[tid * 64 + d]; s += v * v; }
        c2s[tid] = s;
    }
    // zero the buffer iter it+1 will write (idle this iter; launch-serialized)
    if (it <= 7) {
        int gt = blockIdx.x * 128 + tid;
        int nb3 = (it + 1) % 3;
        if (gt < KC * DLAT) g_num[nb3][gt] = 0.f;
        if (gt < KC)        g_den[nb3][gt] = 0.f;
    }
    __syncthreads();   // csrc (rT) reads done before tiles overwrite rT

    float cn[8][4] = {};     // phase-B accumulators (16 k x 64 d per warp)
    float den_acc = 0.f;
    float lacc = 0.f;
    int mw = w * 16;         // both phases: warp's 16-row stripe
    uint32_t eS_u = s2u(eS);

    for (int tile = blockIdx.x; tile < NT; tile += gridDim.x) {
        // ---- stage enc tile via cp.async (64 x 64 fp32 = 1024 float4) ----
        const char* eg = (const char*)(enc + (size_t)tile * (TILE_P * DLAT));
        #pragma unroll
        for (int i = 0; i < 8; i++) {
            int lin = tid + i * 128;           // 1024 float4
            int row = lin >> 4, c4 = lin & 15;
            cp16(eS_u + (row * STRB + c4 * 4) * 4, eg + lin * 16);
        }
        cp_wait_all();
        __syncthreads();
        if (last) {
            if (tid < TILE_P) {
                float s = 0.f;
                #pragma unroll
                for (int d = 0; d < DLAT; d += 4) {
                    float4 v = *(const float4*)&eS[tid * STRB + d];
                    s += v.x * v.x + v.y * v.y + v.z * v.z + v.w * v.w;
                }
                x2s[tid] = s;
            }
            __syncthreads();
        }

        // ---- phase A: dot[p][k], 8 kblocks x 8 nblocks of m16n8k8 ----
        float acc[8][4];
        #pragma unroll
        for (int nb = 0; nb < 8; nb++) { acc[nb][0]=0.f; acc[nb][1]=0.f; acc[nb][2]=0.f; acc[nb][3]=0.f; }
        #pragma unroll
        for (int kb8 = 0; kb8 < 8; kb8++) {
            int kb = kb8 * 8;
            uint32_t a0 = __float_as_uint(eS[(mw + g) * STRB + kb + q]);
            uint32_t a1 = __float_as_uint(eS[(mw + g + 8) * STRB + kb + q]);
            uint32_t a2 = __float_as_uint(eS[(mw + g) * STRB + kb + q + 4]);
            uint32_t a3 = __float_as_uint(eS[(mw + g + 8) * STRB + kb + q + 4]);
            #pragma unroll
            for (int nb = 0; nb < 8; nb++) {
                uint32_t b0 = __float_as_uint(ct[(kb + q) * STRB + nb * 8 + g]);
                uint32_t b1 = __float_as_uint(ct[(kb + q + 4) * STRB + nb * 8 + g]);
                mma8(acc[nb], a0, a1, a2, a3, b0, b1);
            }
        }

        // ---- softmax over k per row; rows (mw+g) and (mw+g+8) ----
        #pragma unroll
        for (int rr = 0; rr < 2; rr++) {
            int p = mw + g + rr * 8;
            float sv[16];
            float mx = -3.402823e38f;
            #pragma unroll
            for (int nb = 0; nb < 8; nb++)
                #pragma unroll
                for (int e = 0; e < 2; e++) {
                    float s = fmaf(2.f, acc[nb][rr * 2 + e], -c2s[nb * 8 + 2 * q + e]);
                    sv[nb * 2 + e] = s;
                    mx = fmaxf(mx, s);
                }
            mx = fmaxf(mx, __shfl_xor_sync(0xffffffffu, mx, 1));
            mx = fmaxf(mx, __shfl_xor_sync(0xffffffffu, mx, 2));
            float sum = 0.f;
            float ev[16];
            #pragma unroll
            for (int j = 0; j < 16; j++) { ev[j] = __expf(sv[j] - mx); sum += ev[j]; }
            sum += __shfl_xor_sync(0xffffffffu, sum, 1);
            sum += __shfl_xor_sync(0xffffffffu, sum, 2);
            if (!last) {
                float iv = 1.f / sum;
                #pragma unroll
                for (int nb = 0; nb < 8; nb++)
                    #pragma unroll
                    for (int e = 0; e < 2; e++)
                        rT[(nb * 8 + 2 * q + e) * STRR + p] = ev[nb * 2 + e] * iv;
            } else {
                float x2p = x2s[p];
                float l = 0.f;
                #pragma unroll
                for (int j = 0; j < 16; j++)
                    l += ev[j] * fmaxf(x2p - sv[j], 0.f);   // d2 = x2 + c2 - 2dot
                lacc += l / sum;
            }
        }

        if (!last) {
            __syncthreads();   // rT complete
            // ---- Cden partials: thread owns k = tid>>1, half (tid&1) of p ----
            {
                const float4* rp = (const float4*)&rT[(tid >> 1) * STRR + (tid & 1) * 32];
                float ds = 0.f;
                #pragma unroll
                for (int j = 0; j < 8; j++) { float4 v = rp[j]; ds += v.x + v.y + v.z + v.w; }
                den_acc += ds;
            }
            // ---- phase B: Cnum[k][d] += r^T enc, 8 pblocks x 8 nblocks ----
            #pragma unroll
            for (int ib = 0; ib < 8; ib++) {
                int pb = ib * 8;
                uint32_t a0 = __float_as_uint(rT[(mw + g) * STRR + pb + q]);
                uint32_t a1 = __float_as_uint(rT[(mw + g + 8) * STRR + pb + q]);
                uint32_t a2 = __float_as_uint(rT[(mw + g) * STRR + pb + q + 4]);
                uint32_t a3 = __float_as_uint(rT[(mw + g + 8) * STRR + pb + q + 4]);
                #pragma unroll
                for (int nb = 0; nb < 8; nb++) {
                    uint32_t b0 = __float_as_uint(eS[(pb + q) * STRB + nb * 8 + g]);
                    uint32_t b1 = __float_as_uint(eS[(pb + q + 4) * STRB + nb * 8 + g]);
                    mma8(cn[nb], a0, a1, a2, a3, b0, b1);
                }
            }
        }
        __syncthreads();   // protect eS/rT before next tile staging
    }

    // ---- block epilogue ----
    if (!last) {
        float* nw = g_num[it % 3];
        #pragma unroll
        for (int nb = 0; nb < 8; nb++) {
            int n0 = nb * 8 + 2 * q;
            atomicAdd(&nw[(mw + g) * 64 + n0],     cn[nb][0]);
            atomicAdd(&nw[(mw + g) * 64 + n0 + 1], cn[nb][1]);
            atomicAdd(&nw[(mw + g + 8) * 64 + n0],     cn[nb][2]);
            atomicAdd(&nw[(mw + g + 8) * 64 + n0 + 1], cn[nb][3]);
        }
        den_acc += __shfl_xor_sync(0xffffffffu, den_acc, 1);
        if ((tid & 1) == 0) atomicAdd(&g_den[it % 3][tid >> 1], den_acc);
    } else {
        #pragma unroll
        for (int o = 16; o; o >>= 1) lacc += __shfl_xor_sync(0xffffffffu, lacc, o);
        if (lane == 0) red[w] = lacc;
        __syncthreads();
        if (tid < 32) {
            float v = (tid < 4) ? red[tid] : 0.f;
            v += __shfl_xor_sync(0xffffffffu, v, 1);
            v += __shfl_xor_sync(0xffffffffu, v, 2);
            if (tid == 0) atomicAdd(&g_loss, v);
        }
    }
}

__global__ void combine_kernel(float* out) {
    out[0] = g_dec * (1.f / (float)(N_PTS * (long long)DDATA))
           + ALPHA_F * g_loss * (1.f / (float)N_PTS);
}

// ---------------------------------------------------------------------------
extern "C" void kernel_launch(void* const* d_in, const int* in_sizes, int n_in,
                              void* d_out, int out_size) {
    const float* X   = (const float*)d_in[0];
    const float* enc = (const float*)d_in[1];
    const float* dcd = (const float*)d_in[2];
    float* out = (float*)d_out;

    cudaFuncSetAttribute(assign_kernel,
                         cudaFuncAttributeMaxDynamicSharedMemorySize, DSMEM_BYTES);

    // C init = enc[:K] (first 64 rows contiguous)
    cudaMemcpyToSymbolAsync(g_C, enc, KC * DLAT * sizeof(float), 0,
                            cudaMemcpyDeviceToDevice, 0);
    init_kernel<<<48, 256>>>();
    dec_kernel<<<1184, 256>>>((const float4*)X, (const float4*)dcd,
                              (N_PTS * DDATA) / 4);
    for (int it = 0; it < 10; it++)
        assign_kernel<<<592, 128, DSMEM_BYTES>>>(enc, it);
    combine_kernel<<<1, 1>>>(out);
}

// round 15
// speedup vs baseline: 1.2377x; 1.2377x over previous
#include <cuda_runtime.h>
#include <cstdint>

// Problem constants (fixed shapes per setup_inputs)
#define N_PTS   65536
#define DLAT    64
#define KC      64
#define DDATA   512
#define ALPHA_F 0.001f
#define EPS_F   1e-8f
#define TILE_P  128
#define NT      (N_PTS / TILE_P)     // 512 tiles of 128 points

// SMEM layout (floats).
//   eS32 stride 72 (fp32): phase-B B-frags bank 8q+g bijective
//   e16/ct16 word-stride 36 (bf16 pairs): frag banks (4g+q) bijective
//   rT stride 132 (fp32): phase-B A-frag bank 4g+q bijective
#define STRB 72
#define STRR 132
#define WS16 36                             // bf16 row stride in 32-bit words
#define OFF_E32 0
#define OFF_E16 (OFF_E32 + 128 * STRB)      // 9216  (128*36 words = 4608 floats)
#define OFF_CT16 (OFF_E16 + 4608)           // 13824 (64*36 words = 2304 floats)
#define OFF_RT (OFF_CT16 + 2304)            // 16128
#define OFF_C2 (OFF_RT + 64 * STRR)         // 24576
#define OFF_X2 (OFF_C2 + 64)                // 24640
#define OFF_RED (OFF_X2 + 128)              // 24768
#define SMEM_FLOATS (OFF_RED + 8)           // 24776
#define DSMEM_BYTES (SMEM_FLOATS * 4)       // 99104 -> 2 CTAs/SM

// Scratch (device globals; no allocation allowed). Triple-buffered accumulators:
// iter j reads (j-1)%3, writes j%3, zeroes (j+1)%3 (idle buffer) — all disjoint.
__device__ float g_C[KC * DLAT];
__device__ float g_num[3][KC * DLAT];
__device__ float g_den[3][KC];
__device__ float g_loss;
__device__ float g_dec;

// ---------------------------------------------------------------------------
// MMA helpers
// ---------------------------------------------------------------------------
__device__ __forceinline__ void mma8(float* c, uint32_t a0, uint32_t a1,
                                     uint32_t a2, uint32_t a3,
                                     uint32_t b0, uint32_t b1) {
    asm volatile(
        "mma.sync.aligned.m16n8k8.row.col.f32.tf32.tf32.f32 "
        "{%0,%1,%2,%3}, {%4,%5,%6,%7}, {%8,%9}, {%0,%1,%2,%3};"
        : "+f"(c[0]), "+f"(c[1]), "+f"(c[2]), "+f"(c[3])
        : "r"(a0), "r"(a1), "r"(a2), "r"(a3), "r"(b0), "r"(b1));
}
__device__ __forceinline__ void mma16(float* c, uint32_t a0, uint32_t a1,
                                      uint32_t a2, uint32_t a3,
                                      uint32_t b0, uint32_t b1) {
    asm volatile(
        "mma.sync.aligned.m16n8k16.row.col.f32.bf16.bf16.f32 "
        "{%0,%1,%2,%3}, {%4,%5,%6,%7}, {%8,%9}, {%0,%1,%2,%3};"
        : "+f"(c[0]), "+f"(c[1]), "+f"(c[2]), "+f"(c[3])
        : "r"(a0), "r"(a1), "r"(a2), "r"(a3), "r"(b0), "r"(b1));
}
// pack two fp32 -> bf16x2 word (lo = first arg, per little-endian frag layout)
__device__ __forceinline__ uint32_t packbf(float lo, float hi) {
    uint32_t r;
    asm("cvt.rn.bf16x2.f32 %0, %1, %2;" : "=r"(r) : "f"(hi), "f"(lo));
    return r;
}

// ---------------------------------------------------------------------------
// Zero accumulators (3 buffers) + scalars
// ---------------------------------------------------------------------------
__global__ void init_kernel() {
    int i = blockIdx.x * blockDim.x + threadIdx.x;
    if (i < 3 * KC * DLAT) ((float*)g_num)[i] = 0.f;
    if (i < 3 * KC)        ((float*)g_den)[i] = 0.f;
    if (i == 0) { g_loss = 0.f; g_dec = 0.f; }
}

// ---------------------------------------------------------------------------
// Decoder loss: sum((X - Dc)^2), float4 grid-stride, block-reduced atomicAdd
// ---------------------------------------------------------------------------
__global__ __launch_bounds__(256) void dec_kernel(const float4* __restrict__ X,
                                                  const float4* __restrict__ Dc,
                                                  int n4) {
    float acc = 0.f;
    int stride = gridDim.x * blockDim.x;
    for (int i = blockIdx.x * blockDim.x + threadIdx.x; i < n4; i += stride) {
        float4 a = X[i], b = Dc[i];
        float d0 = a.x - b.x, d1 = a.y - b.y, d2 = a.z - b.z, d3 = a.w - b.w;
        acc += d0 * d0 + d1 * d1 + d2 * d2 + d3 * d3;
    }
    __shared__ float red[8];
    #pragma unroll
    for (int o = 16; o; o >>= 1) acc += __shfl_xor_sync(0xffffffffu, acc, o);
    int w = threadIdx.x >> 5;
    if ((threadIdx.x & 31) == 0) red[w] = acc;
    __syncthreads();
    if (threadIdx.x < 32) {
        float v = (threadIdx.x < 8) ? red[threadIdx.x] : 0.f;
        #pragma unroll
        for (int o = 4; o; o >>= 1) v += __shfl_xor_sync(0xffffffffu, v, o);
        if (threadIdx.x == 0) atomicAdd(&g_dec, v);
    }
}

// ---------------------------------------------------------------------------
// Fused k-means iteration:
//   phase A: dot[p][k] = enc @ C^T on bf16 m16n8k16 (half the MMAs/LDS of tf32)
//   softmax over k (quad-lane reduction; x2 cancels in logits)
//   phase B: Cnum += r^T enc on tf32 m16n8k8 (scalar B-frags — no transpose)
//   last iter: loss += sum r * max(x2 + c2 - 2 dot, 0)
// 256 threads, 128-pt tiles, 2 CTAs/SM (R13 shape — RF caps 16 warps anyway).
// ---------------------------------------------------------------------------
__global__ __launch_bounds__(256, 2) void assign_kernel(const float* __restrict__ enc,
                                                        int it) {
    extern __shared__ float sm[];
    float*    eS32 = sm + OFF_E32;
    uint32_t* e16  = (uint32_t*)(sm + OFF_E16);
    uint32_t* ct16 = (uint32_t*)(sm + OFF_CT16);
    float*    rT   = sm + OFF_RT;
    float*    c2s  = sm + OFF_C2;
    float*    x2s  = sm + OFF_X2;
    float*    red  = sm + OFF_RED;

    int tid = threadIdx.x, lane = tid & 31, w = tid >> 5;
    int g = lane >> 2, q = lane & 3;
    int last = (it == 9);

    // ---- stage C (fp32) into scratch (rT area), then bf16 ct + c2 ----
    float* csrc = rT;   // 4096 <= 8448 floats
    if (it == 0) {
        for (int i = tid; i < KC * DLAT; i += 256) csrc[i] = g_C[i];
    } else {
        const float* nr = g_num[(it - 1) % 3];
        const float* dr = g_den[(it - 1) % 3];
        for (int i = tid; i < KC * DLAT; i += 256)
            csrc[i] = __fdividef(nr[i], dr[i >> 6] + EPS_F);
    }
    __syncthreads();
    for (int i = tid; i < KC * DLAT / 2; i += 256) {   // 2048 bf16 pairs
        int k = i >> 5, dw = i & 31;                   // d-pair index
        ct16[k * WS16 + dw] = packbf(csrc[k * 64 + dw * 2], csrc[k * 64 + dw * 2 + 1]);
    }
    if (tid < KC) {
        float s = 0.f;
        #pragma unroll 8
        for (int d = 0; d < DLAT; d++) { float v = csrc[tid * 64 + d]; s += v * v; }
        c2s[tid] = s;
    }
    // zero the buffer iter it+1 will write (idle this iter; launch-serialized)
    if (it <= 7) {
        int gt = blockIdx.x * 256 + tid;
        int nb3 = (it + 1) % 3;
        if (gt < KC * DLAT) g_num[nb3][gt] = 0.f;
        if (gt < KC)        g_den[nb3][gt] = 0.f;
    }
    __syncthreads();   // csrc (rT) reads done before tiles overwrite rT

    float cn[4][4] = {};     // phase-B accumulators, persist across tiles
    float den_acc = 0.f;
    float lacc = 0.f;
    int mw = w * 16;                 // phase A: warp's 16-row point stripe
    int mb = w >> 1;                 // phase B: k-block (4 blocks x 2 warps)
    int nbase = (w & 1) * 4;         // phase B: 4 of 8 d-blocks per warp

    for (int tile = blockIdx.x; tile < NT; tile += gridDim.x) {
        // ---- stage enc tile: fp32 copy + packed bf16 copy ----
        const float4* eg = (const float4*)(enc + (size_t)tile * (TILE_P * DLAT));
        #pragma unroll
        for (int i = 0; i < 8; i++) {
            int lin = tid + i * 256;           // 2048 float4
            int row = lin >> 4, c4 = lin & 15;
            float4 v = eg[lin];
            *(float4*)&eS32[row * STRB + c4 * 4] = v;
            e16[row * WS16 + c4 * 2]     = packbf(v.x, v.y);
            e16[row * WS16 + c4 * 2 + 1] = packbf(v.z, v.w);
        }
        __syncthreads();
        if (last) {
            if (tid < TILE_P) {
                float s = 0.f;
                #pragma unroll
                for (int d = 0; d < DLAT; d += 4) {
                    float4 v = *(const float4*)&eS32[tid * STRB + d];
                    s += v.x * v.x + v.y * v.y + v.z * v.z + v.w * v.w;
                }
                x2s[tid] = s;
            }
            __syncthreads();
        }

        // ---- phase A: dot[p][k], 4 ksteps (k16) x 8 nblocks, bf16 ----
        float acc[8][4];
        #pragma unroll
        for (int nb = 0; nb < 8; nb++) { acc[nb][0]=0.f; acc[nb][1]=0.f; acc[nb][2]=0.f; acc[nb][3]=0.f; }
        #pragma unroll
        for (int ks = 0; ks < 4; ks++) {
            int wb = ks * 8;                   // word base along d
            uint32_t a0 = e16[(mw + g) * WS16 + wb + q];
            uint32_t a1 = e16[(mw + g + 8) * WS16 + wb + q];
            uint32_t a2 = e16[(mw + g) * WS16 + wb + q + 4];
            uint32_t a3 = e16[(mw + g + 8) * WS16 + wb + q + 4];
            #pragma unroll
            for (int nb = 0; nb < 8; nb++) {
                uint32_t b0 = ct16[(nb * 8 + g) * WS16 + wb + q];
                uint32_t b1 = ct16[(nb * 8 + g) * WS16 + wb + q + 4];
                mma16(acc[nb], a0, a1, a2, a3, b0, b1);
            }
        }

        // ---- softmax over k per row; rows (mw+g) and (mw+g+8) ----
        #pragma unroll
        for (int rr = 0; rr < 2; rr++) {
            int p = mw + g + rr * 8;
            float sv[16];
            float mx = -3.402823e38f;
            #pragma unroll
            for (int nb = 0; nb < 8; nb++)
                #pragma unroll
                for (int e = 0; e < 2; e++) {
                    float s = fmaf(2.f, acc[nb][rr * 2 + e], -c2s[nb * 8 + 2 * q + e]);
                    sv[nb * 2 + e] = s;
                    mx = fmaxf(mx, s);
                }
            mx = fmaxf(mx, __shfl_xor_sync(0xffffffffu, mx, 1));
            mx = fmaxf(mx, __shfl_xor_sync(0xffffffffu, mx, 2));
            float sum = 0.f;
            float ev[16];
            #pragma unroll
            for (int j = 0; j < 16; j++) { ev[j] = __expf(sv[j] - mx); sum += ev[j]; }
            sum += __shfl_xor_sync(0xffffffffu, sum, 1);
            sum += __shfl_xor_sync(0xffffffffu, sum, 2);
            if (!last) {
                float iv = 1.f / sum;
                #pragma unroll
                for (int nb = 0; nb < 8; nb++)
                    #pragma unroll
                    for (int e = 0; e < 2; e++)
                        rT[(nb * 8 + 2 * q + e) * STRR + p] = ev[nb * 2 + e] * iv;
            } else {
                float x2p = x2s[p];
                float l = 0.f;
                #pragma unroll
                for (int j = 0; j < 16; j++)
                    l += ev[j] * fmaxf(x2p - sv[j], 0.f);   // d2 = x2 + c2 - 2dot
                lacc += l / sum;
            }
        }

        if (!last) {
            __syncthreads();   // rT complete
            // ---- Cden partials: thread owns k = tid>>2, quarter q of p ----
            {
                const float4* rp = (const float4*)&rT[(tid >> 2) * STRR + (tid & 3) * 32];
                float ds = 0.f;
                #pragma unroll
                for (int j = 0; j < 8; j++) { float4 v = rp[j]; ds += v.x + v.y + v.z + v.w; }
                den_acc += ds;
            }
            // ---- phase B: Cnum[k][d] += r^T enc, tf32 k8, 16 pblocks x 4 nb ----
            #pragma unroll
            for (int ib = 0; ib < 16; ib++) {
                int pb = ib * 8;
                uint32_t a0 = __float_as_uint(rT[(mb * 16 + g) * STRR + pb + q]);
                uint32_t a1 = __float_as_uint(rT[(mb * 16 + g + 8) * STRR + pb + q]);
                uint32_t a2 = __float_as_uint(rT[(mb * 16 + g) * STRR + pb + q + 4]);
                uint32_t a3 = __float_as_uint(rT[(mb * 16 + g + 8) * STRR + pb + q + 4]);
                #pragma unroll
                for (int nb4 = 0; nb4 < 4; nb4++) {
                    int nb = nbase + nb4;
                    uint32_t b0 = __float_as_uint(eS32[(pb + q) * STRB + nb * 8 + g]);
                    uint32_t b1 = __float_as_uint(eS32[(pb + q + 4) * STRB + nb * 8 + g]);
                    mma8(cn[nb4], a0, a1, a2, a3, b0, b1);
                }
            }
        }
        __syncthreads();   // protect eS/e16/rT before next tile staging
    }

    // ---- block epilogue ----
    if (!last) {
        float* nw = g_num[it % 3];
        #pragma unroll
        for (int nb4 = 0; nb4 < 4; nb4++) {
            int n0 = (nbase + nb4) * 8 + 2 * q;
            atomicAdd(&nw[(mb * 16 + g) * 64 + n0],     cn[nb4][0]);
            atomicAdd(&nw[(mb * 16 + g) * 64 + n0 + 1], cn[nb4][1]);
            atomicAdd(&nw[(mb * 16 + g + 8) * 64 + n0],     cn[nb4][2]);
            atomicAdd(&nw[(mb * 16 + g + 8) * 64 + n0 + 1], cn[nb4][3]);
        }
        den_acc += __shfl_xor_sync(0xffffffffu, den_acc, 1);
        den_acc += __shfl_xor_sync(0xffffffffu, den_acc, 2);
        if ((tid & 3) == 0) atomicAdd(&g_den[it % 3][tid >> 2], den_acc);
    } else {
        #pragma unroll
        for (int o = 16; o; o >>= 1) lacc += __shfl_xor_sync(0xffffffffu, lacc, o);
        if (lane == 0) red[w] = lacc;
        __syncthreads();
        if (tid < 32) {
            float v = (tid < 8) ? red[tid] : 0.f;
            #pragma unroll
            for (int o = 4; o; o >>= 1) v += __shfl_xor_sync(0xffffffffu, v, o);
            if (tid == 0) atomicAdd(&g_loss, v);
        }
    }
}

__global__ void combine_kernel(float* out) {
    out[0] = g_dec * (1.f / (float)(N_PTS * (long long)DDATA))
           + ALPHA_F * g_loss * (1.f / (float)N_PTS);
}

// ---------------------------------------------------------------------------
extern "C" void kernel_launch(void* const* d_in, const int* in_sizes, int n_in,
                              void* d_out, int out_size) {
    const float* X   = (const float*)d_in[0];
    const float* enc = (const float*)d_in[1];
    const float* dcd = (const float*)d_in[2];
    float* out = (float*)d_out;

    cudaFuncSetAttribute(assign_kernel,
                         cudaFuncAttributeMaxDynamicSharedMemorySize, DSMEM_BYTES);

    // C init = enc[:K] (first 64 rows contiguous)
    cudaMemcpyToSymbolAsync(g_C, enc, KC * DLAT * sizeof(float), 0,
                            cudaMemcpyDeviceToDevice, 0);
    init_kernel<<<48, 256>>>();
    dec_kernel<<<1184, 256>>>((const float4*)X, (const float4*)dcd,
                              (N_PTS * DDATA) / 4);
    for (int it = 0; it < 10; it++)
        assign_kernel<<<296, 256, DSMEM_BYTES>>>(enc, it);
    combine_kernel<<<1, 1>>>(out);
}

// round 16
// speedup vs baseline: 1.3879x; 1.1214x over previous
#include <cuda_runtime.h>
#include <cstdint>

// Problem constants (fixed shapes per setup_inputs)
#define N_PTS   65536
#define DLAT    64
#define KC      64
#define DDATA   512
#define ALPHA_F 0.001f
#define EPS_F   1e-8f
#define TILE_P  128
#define NT      (N_PTS / TILE_P)     // 512 tiles of 128 points
#define GRID_A  296                  // 2 CTAs x 148 SMs — exactly co-resident

// SMEM layout (floats).
//   eS32 stride 72 (fp32): phase-B B-frags bank 8q+g bijective
//   e16/ct16 word-stride 36 (bf16 pairs): frag banks (4g+q) bijective
//   rT stride 132 (fp32): phase-B A-frag bank 4g+q bijective
#define STRB 72
#define STRR 132
#define WS16 36                             // bf16 row stride in 32-bit words
#define OFF_E32 0
#define OFF_E16 (OFF_E32 + 128 * STRB)      // 9216  (128*36 words = 4608 floats)
#define OFF_CT16 (OFF_E16 + 4608)           // 13824 (64*36 words = 2304 floats)
#define OFF_RT (OFF_CT16 + 2304)            // 16128
#define OFF_C2 (OFF_RT + 64 * STRR)         // 24576
#define OFF_X2 (OFF_C2 + 64)                // 24640
#define OFF_RED (OFF_X2 + 128)              // 24768
#define SMEM_FLOATS (OFF_RED + 8)           // 24776
#define DSMEM_BYTES (SMEM_FLOATS * 4)       // 99104 -> 2 CTAs/SM

// Scratch (device globals; no allocation allowed). Triple-buffered accumulators:
// iter j reads (j-1)%3, writes j%3, zeroes (j+1)%3 (idle buffer) — all disjoint.
__device__ float g_C[KC * DLAT];
__device__ float g_num[3][KC * DLAT];
__device__ float g_den[3][KC];
__device__ float g_loss;
__device__ float g_dec;
__device__ unsigned g_barcnt;        // grid-barrier monotonic counter

// ---------------------------------------------------------------------------
// MMA helpers
// ---------------------------------------------------------------------------
__device__ __forceinline__ void mma8(float* c, uint32_t a0, uint32_t a1,
                                     uint32_t a2, uint32_t a3,
                                     uint32_t b0, uint32_t b1) {
    asm volatile(
        "mma.sync.aligned.m16n8k8.row.col.f32.tf32.tf32.f32 "
        "{%0,%1,%2,%3}, {%4,%5,%6,%7}, {%8,%9}, {%0,%1,%2,%3};"
        : "+f"(c[0]), "+f"(c[1]), "+f"(c[2]), "+f"(c[3])
        : "r"(a0), "r"(a1), "r"(a2), "r"(a3), "r"(b0), "r"(b1));
}
__device__ __forceinline__ void mma16(float* c, uint32_t a0, uint32_t a1,
                                      uint32_t a2, uint32_t a3,
                                      uint32_t b0, uint32_t b1) {
    asm volatile(
        "mma.sync.aligned.m16n8k16.row.col.f32.bf16.bf16.f32 "
        "{%0,%1,%2,%3}, {%4,%5,%6,%7}, {%8,%9}, {%0,%1,%2,%3};"
        : "+f"(c[0]), "+f"(c[1]), "+f"(c[2]), "+f"(c[3])
        : "r"(a0), "r"(a1), "r"(a2), "r"(a3), "r"(b0), "r"(b1));
}
// pack two fp32 -> bf16x2 word (lo = first arg, per little-endian frag layout)
__device__ __forceinline__ uint32_t packbf(float lo, float hi) {
    uint32_t r;
    asm("cvt.rn.bf16x2.f32 %0, %1, %2;" : "=r"(r) : "f"(hi), "f"(lo));
    return r;
}
__device__ __forceinline__ unsigned ld_acq(unsigned* p) {
    unsigned v;
    asm volatile("ld.acquire.gpu.u32 %0, [%1];" : "=r"(v) : "l"(p) : "memory");
    return v;
}
// Grid barrier: all GRID_A CTAs arrive; release when counter hits target.
// Bounded spin (hang-proof: a lost arrival degrades to wrong answer, not a
// container timeout). Safe because grid == exactly resident CTA count.
__device__ __forceinline__ void grid_sync(unsigned target) {
    __syncthreads();
    if (threadIdx.x == 0) {
        __threadfence();                      // release g_num/g_den writes
        atomicAdd(&g_barcnt, 1u);
        for (long i = 0; i < (1L << 24); i++) {
            if (ld_acq(&g_barcnt) >= target) break;
            __nanosleep(64);
        }
    }
    __syncthreads();
}

// ---------------------------------------------------------------------------
// Zero accumulators (3 buffers) + scalars + barrier counter
// ---------------------------------------------------------------------------
__global__ void init_kernel() {
    int i = blockIdx.x * blockDim.x + threadIdx.x;
    if (i < 3 * KC * DLAT) ((float*)g_num)[i] = 0.f;
    if (i < 3 * KC)        ((float*)g_den)[i] = 0.f;
    if (i == 0) { g_loss = 0.f; g_dec = 0.f; g_barcnt = 0u; }
}

// ---------------------------------------------------------------------------
// Decoder loss: sum((X - Dc)^2), float4 grid-stride, block-reduced atomicAdd
// ---------------------------------------------------------------------------
__global__ __launch_bounds__(256) void dec_kernel(const float4* __restrict__ X,
                                                  const float4* __restrict__ Dc,
                                                  int n4) {
    float acc = 0.f;
    int stride = gridDim.x * blockDim.x;
    for (int i = blockIdx.x * blockDim.x + threadIdx.x; i < n4; i += stride) {
        float4 a = X[i], b = Dc[i];
        float d0 = a.x - b.x, d1 = a.y - b.y, d2 = a.z - b.z, d3 = a.w - b.w;
        acc += d0 * d0 + d1 * d1 + d2 * d2 + d3 * d3;
    }
    __shared__ float red[8];
    #pragma unroll
    for (int o = 16; o; o >>= 1) acc += __shfl_xor_sync(0xffffffffu, acc, o);
    int w = threadIdx.x >> 5;
    if ((threadIdx.x & 31) == 0) red[w] = acc;
    __syncthreads();
    if (threadIdx.x < 32) {
        float v = (threadIdx.x < 8) ? red[threadIdx.x] : 0.f;
        #pragma unroll
        for (int o = 4; o; o >>= 1) v += __shfl_xor_sync(0xffffffffu, v, o);
        if (threadIdx.x == 0) atomicAdd(&g_dec, v);
    }
}

// ---------------------------------------------------------------------------
// Persistent fused k-means: 10 iterations in ONE launch, separated by device
// grid barriers (no launch/ramp overhead between iterations).
// Per iteration (R15 body):
//   phase A: dot[p][k] = enc @ C^T on bf16 m16n8k16
//   softmax over k (quad-lane reduction; x2 cancels in logits)
//   phase B: Cnum += r^T enc on tf32 m16n8k8
//   last iter: loss += sum r * max(x2 + c2 - 2 dot, 0)
// ---------------------------------------------------------------------------
__global__ __launch_bounds__(256, 2) void assign_persist(const float* __restrict__ enc) {
    extern __shared__ float sm[];
    float*    eS32 = sm + OFF_E32;
    uint32_t* e16  = (uint32_t*)(sm + OFF_E16);
    uint32_t* ct16 = (uint32_t*)(sm + OFF_CT16);
    float*    rT   = sm + OFF_RT;
    float*    c2s  = sm + OFF_C2;
    float*    x2s  = sm + OFF_X2;
    float*    red  = sm + OFF_RED;

    int tid = threadIdx.x, lane = tid & 31, w = tid >> 5;
    int g = lane >> 2, q = lane & 3;
    int mw = w * 16;                 // phase A: warp's 16-row point stripe
    int mb = w >> 1;                 // phase B: k-block (4 blocks x 2 warps)
    int nbase = (w & 1) * 4;         // phase B: 4 of 8 d-blocks per warp

    for (int it = 0; it < 10; it++) {
        int last = (it == 9);

        // ---- stage C (fp32) into scratch (rT area), then bf16 ct + c2 ----
        float* csrc = rT;   // 4096 <= 8448 floats
        if (it == 0) {
            for (int i = tid; i < KC * DLAT; i += 256) csrc[i] = g_C[i];
        } else {
            const float* nr = g_num[(it - 1) % 3];
            const float* dr = g_den[(it - 1) % 3];
            for (int i = tid; i < KC * DLAT; i += 256)
                csrc[i] = __fdividef(nr[i], dr[i >> 6] + EPS_F);
        }
        __syncthreads();
        for (int i = tid; i < KC * DLAT / 2; i += 256) {   // 2048 bf16 pairs
            int k = i >> 5, dw = i & 31;                   // d-pair index
            ct16[k * WS16 + dw] = packbf(csrc[k * 64 + dw * 2], csrc[k * 64 + dw * 2 + 1]);
        }
        if (tid < KC) {
            float s = 0.f;
            #pragma unroll 8
            for (int d = 0; d < DLAT; d++) { float v = csrc[tid * 64 + d]; s += v * v; }
            c2s[tid] = s;
        }
        // zero the buffer iter it+1 will write (idle this iter)
        if (it <= 7) {
            int gt = blockIdx.x * 256 + tid;
            int nb3 = (it + 1) % 3;
            if (gt < KC * DLAT) g_num[nb3][gt] = 0.f;
            if (gt < KC)        g_den[nb3][gt] = 0.f;
        }
        __syncthreads();   // csrc (rT) reads done before tiles overwrite rT

        float cn[4][4] = {};     // phase-B accumulators, persist across tiles
        float den_acc = 0.f;
        float lacc = 0.f;

        for (int tile = blockIdx.x; tile < NT; tile += GRID_A) {
            // ---- stage enc tile: fp32 copy + packed bf16 copy ----
            const float4* eg = (const float4*)(enc + (size_t)tile * (TILE_P * DLAT));
            #pragma unroll
            for (int i = 0; i < 8; i++) {
                int lin = tid + i * 256;           // 2048 float4
                int row = lin >> 4, c4 = lin & 15;
                float4 v = eg[lin];
                *(float4*)&eS32[row * STRB + c4 * 4] = v;
                e16[row * WS16 + c4 * 2]     = packbf(v.x, v.y);
                e16[row * WS16 + c4 * 2 + 1] = packbf(v.z, v.w);
            }
            __syncthreads();
            if (last) {
                if (tid < TILE_P) {
                    float s = 0.f;
                    #pragma unroll
                    for (int d = 0; d < DLAT; d += 4) {
                        float4 v = *(const float4*)&eS32[tid * STRB + d];
                        s += v.x * v.x + v.y * v.y + v.z * v.z + v.w * v.w;
                    }
                    x2s[tid] = s;
                }
                __syncthreads();
            }

            // ---- phase A: dot[p][k], 4 ksteps (k16) x 8 nblocks, bf16 ----
            float acc[8][4];
            #pragma unroll
            for (int nb = 0; nb < 8; nb++) { acc[nb][0]=0.f; acc[nb][1]=0.f; acc[nb][2]=0.f; acc[nb][3]=0.f; }
            #pragma unroll
            for (int ks = 0; ks < 4; ks++) {
                int wb = ks * 8;                   // word base along d
                uint32_t a0 = e16[(mw + g) * WS16 + wb + q];
                uint32_t a1 = e16[(mw + g + 8) * WS16 + wb + q];
                uint32_t a2 = e16[(mw + g) * WS16 + wb + q + 4];
                uint32_t a3 = e16[(mw + g + 8) * WS16 + wb + q + 4];
                #pragma unroll
                for (int nb = 0; nb < 8; nb++) {
                    uint32_t b0 = ct16[(nb * 8 + g) * WS16 + wb + q];
                    uint32_t b1 = ct16[(nb * 8 + g) * WS16 + wb + q + 4];
                    mma16(acc[nb], a0, a1, a2, a3, b0, b1);
                }
            }

            // ---- softmax over k per row; rows (mw+g) and (mw+g+8) ----
            #pragma unroll
            for (int rr = 0; rr < 2; rr++) {
                int p = mw + g + rr * 8;
                float sv[16];
                float mx = -3.402823e38f;
                #pragma unroll
                for (int nb = 0; nb < 8; nb++)
                    #pragma unroll
                    for (int e = 0; e < 2; e++) {
                        float s = fmaf(2.f, acc[nb][rr * 2 + e], -c2s[nb * 8 + 2 * q + e]);
                        sv[nb * 2 + e] = s;
                        mx = fmaxf(mx, s);
                    }
                mx = fmaxf(mx, __shfl_xor_sync(0xffffffffu, mx, 1));
                mx = fmaxf(mx, __shfl_xor_sync(0xffffffffu, mx, 2));
                float sum = 0.f;
                float ev[16];
                #pragma unroll
                for (int j = 0; j < 16; j++) { ev[j] = __expf(sv[j] - mx); sum += ev[j]; }
                sum += __shfl_xor_sync(0xffffffffu, sum, 1);
                sum += __shfl_xor_sync(0xffffffffu, sum, 2);
                if (!last) {
                    float iv = 1.f / sum;
                    #pragma unroll
                    for (int nb = 0; nb < 8; nb++)
                        #pragma unroll
                        for (int e = 0; e < 2; e++)
                            rT[(nb * 8 + 2 * q + e) * STRR + p] = ev[nb * 2 + e] * iv;
                } else {
                    float x2p = x2s[p];
                    float l = 0.f;
                    #pragma unroll
                    for (int j = 0; j < 16; j++)
                        l += ev[j] * fmaxf(x2p - sv[j], 0.f);   // d2 = x2+c2-2dot
                    lacc += l / sum;
                }
            }

            if (!last) {
                __syncthreads();   // rT complete
                // ---- Cden partials: thread owns k = tid>>2, quarter q of p ----
                {
                    const float4* rp = (const float4*)&rT[(tid >> 2) * STRR + (tid & 3) * 32];
                    float ds = 0.f;
                    #pragma unroll
                    for (int j = 0; j < 8; j++) { float4 v = rp[j]; ds += v.x + v.y + v.z + v.w; }
                    den_acc += ds;
                }
                // ---- phase B: Cnum[k][d] += r^T enc, tf32 k8, 16 pb x 4 nb ----
                #pragma unroll
                for (int ib = 0; ib < 16; ib++) {
                    int pb = ib * 8;
                    uint32_t a0 = __float_as_uint(rT[(mb * 16 + g) * STRR + pb + q]);
                    uint32_t a1 = __float_as_uint(rT[(mb * 16 + g + 8) * STRR + pb + q]);
                    uint32_t a2 = __float_as_uint(rT[(mb * 16 + g) * STRR + pb + q + 4]);
                    uint32_t a3 = __float_as_uint(rT[(mb * 16 + g + 8) * STRR + pb + q + 4]);
                    #pragma unroll
                    for (int nb4 = 0; nb4 < 4; nb4++) {
                        int nb = nbase + nb4;
                        uint32_t b0 = __float_as_uint(eS32[(pb + q) * STRB + nb * 8 + g]);
                        uint32_t b1 = __float_as_uint(eS32[(pb + q + 4) * STRB + nb * 8 + g]);
                        mma8(cn[nb4], a0, a1, a2, a3, b0, b1);
                    }
                }
            }
            __syncthreads();   // protect eS/e16/rT before next tile staging
        }

        // ---- iteration epilogue ----
        if (!last) {
            float* nw = g_num[it % 3];
            #pragma unroll
            for (int nb4 = 0; nb4 < 4; nb4++) {
                int n0 = (nbase + nb4) * 8 + 2 * q;
                atomicAdd(&nw[(mb * 16 + g) * 64 + n0],     cn[nb4][0]);
                atomicAdd(&nw[(mb * 16 + g) * 64 + n0 + 1], cn[nb4][1]);
                atomicAdd(&nw[(mb * 16 + g + 8) * 64 + n0],     cn[nb4][2]);
                atomicAdd(&nw[(mb * 16 + g + 8) * 64 + n0 + 1], cn[nb4][3]);
            }
            den_acc += __shfl_xor_sync(0xffffffffu, den_acc, 1);
            den_acc += __shfl_xor_sync(0xffffffffu, den_acc, 2);
            if ((tid & 3) == 0) atomicAdd(&g_den[it % 3][tid >> 2], den_acc);
            grid_sync((unsigned)(GRID_A * (it + 1)));   // release writes, wait all
        } else {
            #pragma unroll
            for (int o = 16; o; o >>= 1) lacc += __shfl_xor_sync(0xffffffffu, lacc, o);
            if (lane == 0) red[w] = lacc;
            __syncthreads();
            if (tid < 32) {
                float v = (tid < 8) ? red[tid] : 0.f;
                #pragma unroll
                for (int o = 4; o; o >>= 1) v += __shfl_xor_sync(0xffffffffu, v, o);
                if (tid == 0) atomicAdd(&g_loss, v);
            }
        }
    }
}

__global__ void combine_kernel(float* out) {
    out[0] = g_dec * (1.f / (float)(N_PTS * (long long)DDATA))
           + ALPHA_F * g_loss * (1.f / (float)N_PTS);
}

// ---------------------------------------------------------------------------
extern "C" void kernel_launch(void* const* d_in, const int* in_sizes, int n_in,
                              void* d_out, int out_size) {
    const float* X   = (const float*)d_in[0];
    const float* enc = (const float*)d_in[1];
    const float* dcd = (const float*)d_in[2];
    float* out = (float*)d_out;

    cudaFuncSetAttribute(assign_persist,
                         cudaFuncAttributeMaxDynamicSharedMemorySize, DSMEM_BYTES);

    // C init = enc[:K] (first 64 rows contiguous)
    cudaMemcpyToSymbolAsync(g_C, enc, KC * DLAT * sizeof(float), 0,
                            cudaMemcpyDeviceToDevice, 0);
    init_kernel<<<48, 256>>>();
    dec_kernel<<<1184, 256>>>((const float4*)X, (const float4*)dcd,
                              (N_PTS * DDATA) / 4);
    assign_persist<<<GRID_A, 256, DSMEM_BYTES>>>(enc);
    combine_kernel<<<1, 1>>>(out);
}